// round 11
// baseline (speedup 1.0000x reference)
#include <cuda_runtime.h>
#include <cuda_fp16.h>
#include <cstdint>

// NeiAttention, single fused persistent kernel (round 11).
// 148 CTAs x 512 thr, 1 CTA/SM. W fp16 resident in smem; per 8-node group:
//   prefetch A (regs) | y = x@W (MMA) | logits=a.y, softmax (fp32) | z=sum(alpha*a) | out=z@W^T+b (MMA)
// A held fp16 in smem (ping-pong); prefetched LDGs ride in registers across compute.

#define NT 2048
#define NC 148

// smem byte offsets
#define WB   0          // W fp16 [128 d][192 k], row stride 400 B
#define AB0  51200      // A fp16 [128 r][192 k], stride 400 B (buf 0)
#define AB1  102400     // buf 1
#define XB0  153600     // x fp16 [16 r][128 d], stride 272 B (buf 0; rows 8-15 garbage)
#define XB1  157952
#define ZB   162304     // z fp16 [16 n][192 k], stride 400 B (rows 8-15 garbage)
#define YB   168704     // y fp32 [8 n][192 k]
#define LOGB 174848     // 128 f32 logits
#define EB   175360     // 128 f32 exp
#define ALB  175872     // 128 f32 alpha
#define BIB  176384     // 128 f32 bias
#define SMEM_BYTES 176896

__device__ __forceinline__ uint32_t smem_u32(const void* p) {
    uint32_t a;
    asm("{ .reg .u64 t; cvta.to.shared.u64 t, %1; cvt.u32.u64 %0, t; }" : "=r"(a) : "l"(p));
    return a;
}
__device__ __forceinline__ uint32_t pack_f16x2(float lo, float hi) {
    uint32_t r;
    asm("cvt.rn.f16x2.f32 %0, %1, %2;" : "=r"(r) : "f"(hi), "f"(lo));
    return r;
}
__device__ __forceinline__ void ldsm4(uint32_t r[4], uint32_t addr) {
    asm volatile("ldmatrix.sync.aligned.m8n8.x4.shared.b16 {%0,%1,%2,%3}, [%4];"
                 : "=r"(r[0]), "=r"(r[1]), "=r"(r[2]), "=r"(r[3]) : "r"(addr));
}
__device__ __forceinline__ void ldsm4t(uint32_t r[4], uint32_t addr) {
    asm volatile("ldmatrix.sync.aligned.m8n8.x4.trans.shared.b16 {%0,%1,%2,%3}, [%4];"
                 : "=r"(r[0]), "=r"(r[1]), "=r"(r[2]), "=r"(r[3]) : "r"(addr));
}
__device__ __forceinline__ void mma_f16(float d[4], const uint32_t a[4],
                                        uint32_t b0, uint32_t b1) {
    asm volatile(
        "mma.sync.aligned.m16n8k16.row.col.f32.f16.f16.f32 "
        "{%0,%1,%2,%3}, {%4,%5,%6,%7}, {%8,%9}, {%0,%1,%2,%3};"
        : "+f"(d[0]), "+f"(d[1]), "+f"(d[2]), "+f"(d[3])
        : "r"(a[0]), "r"(a[1]), "r"(a[2]), "r"(a[3]), "r"(b0), "r"(b1));
}
__device__ __forceinline__ float shflx(float v, int m) { return __shfl_xor_sync(0xffffffffu, v, m); }

__device__ __forceinline__ void sts_f16x4(char* dst, float4 v) {
    uint2 w;
    w.x = pack_f16x2(v.x, v.y);
    w.y = pack_f16x2(v.z, v.w);
    *(uint2*)dst = w;
}

__global__ __launch_bounds__(512, 1)
void nei_fused(const float* __restrict__ x,
               const float* __restrict__ rel,
               const float* __restrict__ nod,
               const float* __restrict__ Ww,
               const float* __restrict__ Wb,
               float* __restrict__ out)
{
    extern __shared__ char sm[];
    const uint32_t sb = smem_u32(sm);
    const int tid = threadIdx.x;
    const int wid = tid >> 5, lid = tid & 31;
    const int g = lid >> 2, t4 = lid & 3;
    const int sel = lid >> 3, lr = lid & 7;

    float* sLog = (float*)(sm + LOGB);
    float* sE   = (float*)(sm + EB);
    float* sAl  = (float*)(sm + ALB);
    const float* sBias = (const float*)(sm + BIB);

    // ---- stage W (fp32 -> fp16) once + bias ----
    {
        const float4* Wv = (const float4*)Ww;     // [128][192] -> 6144 float4
        #pragma unroll
        for (int it = 0; it < 12; it++) {
            int idx = tid + it * 512;
            int d = idx / 48, c = idx - d * 48;
            sts_f16x4(sm + WB + d * 400 + c * 8, Wv[idx]);
        }
        if (tid < 128) ((float*)(sm + BIB))[tid] = Wb[tid];
    }
    // ---- stage first group's A + x into buf 0 ----
    {
        const int t0 = blockIdx.x;
        const float4* rp = (const float4*)(rel + (size_t)t0 * 8192);
        const float4* np = (const float4*)(nod + (size_t)t0 * 16384);
        #pragma unroll
        for (int it = 0; it < 4; it++) {
            int idx = tid + it * 512;             // 2048: r*16 + c
            int r = idx >> 4, c = idx & 15;
            sts_f16x4(sm + AB0 + r * 400 + c * 8, rp[idx]);
        }
        #pragma unroll
        for (int it = 0; it < 8; it++) {
            int idx = tid + it * 512;             // 4096: r*32 + c
            int r = idx >> 5, c = idx & 31;
            sts_f16x4(sm + AB0 + r * 400 + 128 + c * 8, np[idx]);
        }
        if (tid < 256) {
            float4 v = ((const float4*)(x + (size_t)t0 * 1024))[tid];
            int r = tid >> 5, c = tid & 31;
            sts_f16x4(sm + XB0 + r * 272 + c * 8, v);
        }
    }
    __syncthreads();

    // fixed fragment addresses (W-side / z-side)
    const uint32_t bWy = sb + WB + (uint32_t)((lid & 7) + ((lid >> 3) & 1) * 8) * 400u
                         + (uint32_t)(wid * 16 + (lid >> 4) * 8) * 2u;   // trans B, wid<12
    const uint32_t bWo = sb + WB + (uint32_t)(wid * 8 + lr) * 400u + (uint32_t)sel * 16u;
    const uint32_t aZ  = sb + ZB + (uint32_t)((sel & 1) * 8 + lr) * 400u
                         + (uint32_t)(sel >> 1) * 16u;

    int par = 0;
    for (int t = blockIdx.x; t < NT; t += NC, par ^= 1) {
        const int tn = t + NC;
        const bool pf = (tn < NT);

        // ---- prefetch next group's A/x into registers (DRAM in flight during compute) ----
        float4 vr0, vr1, vr2, vr3;
        float4 vn0, vn1, vn2, vn3, vn4, vn5, vn6, vn7;
        float4 vx;
        if (pf) {
            const float4* rp = (const float4*)(rel + (size_t)tn * 8192);
            const float4* np = (const float4*)(nod + (size_t)tn * 16384);
            vr0 = rp[tid];        vr1 = rp[tid + 512];
            vr2 = rp[tid + 1024]; vr3 = rp[tid + 1536];
            vn0 = np[tid];        vn1 = np[tid + 512];
            vn2 = np[tid + 1024]; vn3 = np[tid + 1536];
            vn4 = np[tid + 2048]; vn5 = np[tid + 2560];
            vn6 = np[tid + 3072]; vn7 = np[tid + 3584];
            if (tid < 256) vx = ((const float4*)(x + (size_t)tn * 1024))[tid];
        }

        const uint32_t abB = sb + (par ? AB1 : AB0);
        const uint32_t xbB = sb + (par ? XB1 : XB0);
        const char*    abC = sm + (par ? AB1 : AB0);

        // ---- phase 1: y = x @ W  (warps 0..11, cols 16*wid .. +16) ----
        if (wid < 12) {
            const uint32_t aX = xbB + (uint32_t)((sel & 1) * 8 + lr) * 272u
                                + (uint32_t)(sel >> 1) * 16u;
            float y0[4] = {0.f, 0.f, 0.f, 0.f};
            float y1[4] = {0.f, 0.f, 0.f, 0.f};
            #pragma unroll
            for (int ks = 0; ks < 8; ks++) {       // K = 128 over d
                uint32_t a[4], bt[4];
                ldsm4(a, aX + ks * 32);
                ldsm4t(bt, bWy + ks * 6400);
                mma_f16(y0, a, bt[0], bt[1]);
                mma_f16(y1, a, bt[2], bt[3]);
            }
            float* yp = (float*)(sm + YB) + g * 192 + wid * 16 + 2 * t4;
            float2 s0 = { y0[0], y0[1] };
            float2 s1 = { y1[0], y1[1] };
            *(float2*)yp       = s0;
            *(float2*)(yp + 8) = s1;
        }
        __syncthreads();

        // ---- phase 2: logits = a . y  (4 threads per row) ----
        {
            int row = tid >> 2, q = tid & 3;
            const half2*  ap = (const half2*)(abC + row * 400 + q * 96);
            const float2* yp = (const float2*)(sm + YB + ((row >> 4) * 192 + q * 48) * 4);
            float s = 0.f;
            #pragma unroll
            for (int kk = 0; kk < 24; kk++) {
                float2 a2 = __half22float2(ap[kk]);
                float2 yv = yp[kk];
                s += a2.x * yv.x + a2.y * yv.y;
            }
            s += shflx(s, 1);
            s += shflx(s, 2);
            if (q == 0) sLog[row] = s * 0.08838834764831845f;   // 1/sqrt(128)
        }
        __syncthreads();

        // ---- phase 3: softmax over S=16 per node ----
        float e = 0.f;
        if (tid < 128) {
            int base = tid & ~15;
            float m = -1e30f;
            #pragma unroll
            for (int q = 0; q < 16; q++) m = fmaxf(m, sLog[base + q]);
            e = __expf(sLog[tid] - m);
            sE[tid] = e;
        }
        __syncthreads();
        if (tid < 128) {
            int base = tid & ~15;
            float den = 0.f;
            #pragma unroll
            for (int q = 0; q < 16; q++) den += sE[base + q];
            sAl[tid] = e / den;
        }
        __syncthreads();

        // ---- phase 4: z[n][k-pair] = sum_s alpha * a  -> fp16 ----
        #pragma unroll
        for (int p2 = 0; p2 < 2; p2++) {
            int u = tid + 512 * p2;                // 0..767 = n*96 + kp
            if (u < 768) {
                int n = u / 96, kp = u - n * 96;
                const half2* ap = (const half2*)abC + (16 * n) * 100 + kp;
                const float* al = sAl + 16 * n;
                float z0 = 0.f, z1 = 0.f;
                #pragma unroll
                for (int s = 0; s < 16; s++) {
                    float2 av = __half22float2(ap[s * 100]);
                    float  a  = al[s];
                    z0 += a * av.x;
                    z1 += a * av.y;
                }
                *(uint32_t*)(sm + ZB + n * 400 + kp * 4) = pack_f16x2(z0, z1);
            }
        }
        __syncthreads();

        // ---- phase 5: out = z @ W^T + b  (all 16 warps, cols 8*wid .. +8) ----
        {
            float o[4] = {0.f, 0.f, 0.f, 0.f};
            #pragma unroll
            for (int k2 = 0; k2 < 6; k2++) {       // 2 ksteps per iter, K = 192
                uint32_t b[4], a0[4], a1[4];
                ldsm4(b, bWo + k2 * 64);
                ldsm4(a0, aZ + (2 * k2) * 32);
                mma_f16(o, a0, b[0], b[1]);
                ldsm4(a1, aZ + (2 * k2 + 1) * 32);
                mma_f16(o, a1, b[2], b[3]);
            }
            int col = wid * 8 + 2 * t4;
            float2 w;
            w.x = o[0] + sBias[col];
            w.y = o[1] + sBias[col + 1];
            *(float2*)(out + (size_t)(t * 8 + g) * 128 + col) = w;
        }

        // ---- drain prefetch into the other buffer ----
        if (pf) {
            const uint32_t ab2 = sb + (par ? AB0 : AB1);
            char* a2 = sm + (par ? AB0 : AB1);
            char* x2 = sm + (par ? XB0 : XB1);
            (void)ab2;
            {   // rel: idx = tid + 512*it, r = idx>>4, c = idx&15
                int r, c;
                r = (tid) >> 4;          c = (tid) & 15;          sts_f16x4(a2 + r * 400 + c * 8, vr0);
                r = (tid + 512) >> 4;    c = (tid + 512) & 15;    sts_f16x4(a2 + r * 400 + c * 8, vr1);
                r = (tid + 1024) >> 4;   c = (tid + 1024) & 15;   sts_f16x4(a2 + r * 400 + c * 8, vr2);
                r = (tid + 1536) >> 4;   c = (tid + 1536) & 15;   sts_f16x4(a2 + r * 400 + c * 8, vr3);
            }
            {   // node: r = idx>>5, c = idx&31
                int r, c;
                r = (tid) >> 5;          c = (tid) & 31;          sts_f16x4(a2 + r * 400 + 128 + c * 8, vn0);
                r = (tid + 512) >> 5;    c = (tid + 512) & 31;    sts_f16x4(a2 + r * 400 + 128 + c * 8, vn1);
                r = (tid + 1024) >> 5;   c = (tid + 1024) & 31;   sts_f16x4(a2 + r * 400 + 128 + c * 8, vn2);
                r = (tid + 1536) >> 5;   c = (tid + 1536) & 31;   sts_f16x4(a2 + r * 400 + 128 + c * 8, vn3);
                r = (tid + 2048) >> 5;   c = (tid + 2048) & 31;   sts_f16x4(a2 + r * 400 + 128 + c * 8, vn4);
                r = (tid + 2560) >> 5;   c = (tid + 2560) & 31;   sts_f16x4(a2 + r * 400 + 128 + c * 8, vn5);
                r = (tid + 3072) >> 5;   c = (tid + 3072) & 31;   sts_f16x4(a2 + r * 400 + 128 + c * 8, vn6);
                r = (tid + 3584) >> 5;   c = (tid + 3584) & 31;   sts_f16x4(a2 + r * 400 + 128 + c * 8, vn7);
            }
            if (tid < 256) {
                int r = tid >> 5, c = tid & 31;
                sts_f16x4(x2 + r * 272 + c * 8, vx);
            }
        }
        __syncthreads();
    }
}

extern "C" void kernel_launch(void* const* d_in, const int* in_sizes, int n_in,
                              void* d_out, int out_size)
{
    const float* x          = (const float*)d_in[0];
    const float* x_nei_rel  = (const float*)d_in[1];
    const float* x_nei_node = (const float*)d_in[2];
    const float* W1_w       = (const float*)d_in[3];
    const float* W1_b       = (const float*)d_in[4];
    float* out = (float*)d_out;

    cudaFuncSetAttribute(nei_fused,
                         cudaFuncAttributeMaxDynamicSharedMemorySize, SMEM_BYTES);

    nei_fused<<<NC, 512, SMEM_BYTES>>>(x, x_nei_rel, x_nei_node, W1_w, W1_b, out);
}